// round 4
// baseline (speedup 1.0000x reference)
#include <cuda_runtime.h>

#define NN 100000
#define EE 1600000
#define BB 1024
#define SCAN_B 98   // ceil(NN/1024)

// ---------------- scratch (device globals) -----------------------------------
__device__ __align__(128) float d_h   [NN * 128];
__device__ __align__(128) float d_as  [NN * 4];
__device__ __align__(128) float d_ad  [NN * 4];
__device__ __align__(128) float d_gat [NN * 128];
__device__ __align__(128) float d_h1  [NN * 64];
__device__ __align__(128) float d_o2  [NN * 64];
__device__ __align__(128) float d_h2  [NN * 128];
__device__ __align__(128) float d_dinv[NN];
__device__ __align__(128) float d_pool[BB * 128];
__device__ __align__(128) float d_cnt [BB];
__device__ __align__(128) float d_s1  [BB * 64 * 18];
__device__ __align__(128) float d_s2  [BB * 64 * 16];
__device__ __align__(128) float d_fc  [BB * 64];
__device__ __align__(128) int   d_degi[NN];
__device__ __align__(128) int   d_off [NN];
__device__ __align__(128) int   d_cur [NN];
__device__ __align__(128) int   d_csr [EE];
__device__ __align__(128) int   d_bsum [SCAN_B];
__device__ __align__(128) int   d_bbase[SCAN_B];

__device__ __forceinline__ float lrelu(float x, float s) { return x < 0.f ? s * x : x; }

__device__ __forceinline__ float fsel4(float4 v, int h) {
    return h == 0 ? v.x : (h == 1 ? v.y : (h == 2 ? v.z : v.w));
}

__device__ __forceinline__ void redAdd4(float* p, float a, float b, float c, float d) {
    asm volatile("red.global.add.v4.f32 [%0], {%1,%2,%3,%4};"
                 :: "l"(p), "f"(a), "f"(b), "f"(c), "f"(d) : "memory");
}

// ---------------- init --------------------------------------------------------
__global__ void k_init() {
    int i = blockIdx.x * 256 + threadIdx.x;
    if (i < NN)       d_degi[i] = 0;
    if (i < BB * 128) d_pool[i] = 0.f;
    if (i < BB)       d_cnt[i]  = 0.f;
}

// ---------------- node transform ----------------------------------------------
__global__ void k_node(const float* __restrict__ x, const float* __restrict__ Wg,
                       const float* __restrict__ atts, const float* __restrict__ attd) {
    int idx = blockIdx.x * 256 + threadIdx.x;      // NN*128 threads
    int node = idx >> 7, f = idx & 127;
    float acc = 0.f;
    #pragma unroll
    for (int k = 0; k < 9; k++) acc += x[node * 9 + k] * Wg[k * 128 + f];
    d_h[idx] = acc;
    int head = f >> 5, c = f & 31;
    float ts = acc * atts[head * 32 + c];
    float td = acc * attd[head * 32 + c];
    #pragma unroll
    for (int off = 16; off > 0; off >>= 1) {
        ts += __shfl_xor_sync(0xffffffffu, ts, off);
        td += __shfl_xor_sync(0xffffffffu, td, off);
    }
    if ((threadIdx.x & 31) == 0) {
        d_as[node * 4 + head] = ts;
        d_ad[node * 4 + head] = td;
    }
}

// ---------------- degree histogram + batch counts ------------------------------
__global__ void k_hist(const int* __restrict__ ei, const int* __restrict__ batch) {
    int idx = blockIdx.x * 256 + threadIdx.x;
    if (idx < EE) atomicAdd(&d_degi[ei[EE + idx]], 1);
    if (idx < NN) atomicAdd(&d_cnt[batch[idx]], 1.0f);
}

// ---------------- scan ---------------------------------------------------------
__global__ void k_scanA() {
    __shared__ int sm[1024];
    int i = blockIdx.x * 1024 + threadIdx.x;
    int v = (i < NN) ? d_degi[i] : 0;
    sm[threadIdx.x] = v;
    __syncthreads();
    for (int off = 1; off < 1024; off <<= 1) {
        int t = (threadIdx.x >= off) ? sm[threadIdx.x - off] : 0;
        __syncthreads();
        sm[threadIdx.x] += t;
        __syncthreads();
    }
    if (i < NN) d_off[i] = sm[threadIdx.x] - v;
    if (threadIdx.x == 1023) d_bsum[blockIdx.x] = sm[1023];
}

__global__ void k_scanB() {
    __shared__ int sm[128];
    int t = threadIdx.x;
    int v = (t < SCAN_B) ? d_bsum[t] : 0;
    sm[t] = v;
    __syncthreads();
    for (int off = 1; off < 128; off <<= 1) {
        int tv = (t >= off) ? sm[t - off] : 0;
        __syncthreads();
        sm[t] += tv;
        __syncthreads();
    }
    if (t < SCAN_B) d_bbase[t] = sm[t] - v;   // exclusive
}

__global__ void k_scanC() {
    int i = blockIdx.x * 1024 + threadIdx.x;
    if (i < NN) {
        int o = d_off[i] + d_bbase[blockIdx.x];
        d_off[i] = o;
        d_cur[i] = o;
        d_dinv[i] = rsqrtf((float)(d_degi[i] + 1));
    }
}

// ---------------- CSR fill ------------------------------------------------------
__global__ void k_fill(const int* __restrict__ ei) {
    int idx = blockIdx.x * 256 + threadIdx.x;
    if (idx < EE) {
        int dst = ei[EE + idx];
        int p = atomicAdd(&d_cur[dst], 1);
        d_csr[p] = ei[idx];
    }
}

// ---------------- fused GAT: exact softmax, 3-phase, warp per node -------------
__global__ void k_gat(const float* __restrict__ bg) {
    __shared__ float s_alpha[8][128];
    __shared__ int   s_src[8][32];
    int gw = (blockIdx.x * 256 + threadIdx.x) >> 5;
    if (gw >= NN) return;
    int lane = threadIdx.x & 31;
    int w = (threadIdx.x >> 5) & 7;
    int h = lane >> 3;
    int d = gw;

    float4 ad4  = *(const float4*)&d_ad[d * 4];
    float4 as_d = *(const float4*)&d_as[d * 4];
    float4 es;  // self logit
    es.x = lrelu(as_d.x + ad4.x, 0.2f); es.y = lrelu(as_d.y + ad4.y, 0.2f);
    es.z = lrelu(as_d.z + ad4.z, 0.2f); es.w = lrelu(as_d.w + ad4.w, 0.2f);

    int start = d_off[d];
    int cntE  = d_degi[d];

    // phase 0: max (self logit participates; max is idempotent across lanes)
    float4 m4 = es;
    for (int p0 = 0; p0 < cntE; p0 += 32) {
        if (p0 + lane < cntE) {
            int src = d_csr[start + p0 + lane];
            float4 av = *(const float4*)&d_as[src * 4];
            m4.x = fmaxf(m4.x, lrelu(av.x + ad4.x, 0.2f));
            m4.y = fmaxf(m4.y, lrelu(av.y + ad4.y, 0.2f));
            m4.z = fmaxf(m4.z, lrelu(av.z + ad4.z, 0.2f));
            m4.w = fmaxf(m4.w, lrelu(av.w + ad4.w, 0.2f));
        }
    }
    #pragma unroll
    for (int off = 16; off > 0; off >>= 1) {
        m4.x = fmaxf(m4.x, __shfl_xor_sync(0xffffffffu, m4.x, off));
        m4.y = fmaxf(m4.y, __shfl_xor_sync(0xffffffffu, m4.y, off));
        m4.z = fmaxf(m4.z, __shfl_xor_sync(0xffffffffu, m4.z, off));
        m4.w = fmaxf(m4.w, __shfl_xor_sync(0xffffffffu, m4.w, off));
    }

    // phase 1: sum of exp (self term added ONCE, after the reduction)
    float4 s4 = make_float4(0.f, 0.f, 0.f, 0.f);
    for (int p0 = 0; p0 < cntE; p0 += 32) {
        if (p0 + lane < cntE) {
            int src = d_csr[start + p0 + lane];
            float4 av = *(const float4*)&d_as[src * 4];
            s4.x += __expf(lrelu(av.x + ad4.x, 0.2f) - m4.x);
            s4.y += __expf(lrelu(av.y + ad4.y, 0.2f) - m4.y);
            s4.z += __expf(lrelu(av.z + ad4.z, 0.2f) - m4.z);
            s4.w += __expf(lrelu(av.w + ad4.w, 0.2f) - m4.w);
        }
    }
    #pragma unroll
    for (int off = 16; off > 0; off >>= 1) {
        s4.x += __shfl_xor_sync(0xffffffffu, s4.x, off);
        s4.y += __shfl_xor_sync(0xffffffffu, s4.y, off);
        s4.z += __shfl_xor_sync(0xffffffffu, s4.z, off);
        s4.w += __shfl_xor_sync(0xffffffffu, s4.w, off);
    }
    // self term exactly once (uniform across lanes: m4 is fully reduced here)
    s4.x += __expf(es.x - m4.x); s4.y += __expf(es.y - m4.y);
    s4.z += __expf(es.z - m4.z); s4.w += __expf(es.w - m4.w);
    float4 inv4;
    inv4.x = 1.0f / (s4.x + 1e-16f); inv4.y = 1.0f / (s4.y + 1e-16f);
    inv4.z = 1.0f / (s4.z + 1e-16f); inv4.w = 1.0f / (s4.w + 1e-16f);

    // phase 2: weighted accumulation
    float aself = __expf(fsel4(es, h) - fsel4(m4, h)) * fsel4(inv4, h);
    float4 acc = *(const float4*)&d_h[d * 128 + lane * 4];
    acc.x *= aself; acc.y *= aself; acc.z *= aself; acc.w *= aself;

    for (int p0 = 0; p0 < cntE; p0 += 32) {
        if (p0 + lane < cntE) {
            int src = d_csr[start + p0 + lane];
            float4 av = *(const float4*)&d_as[src * 4];
            float4 a4;
            a4.x = __expf(lrelu(av.x + ad4.x, 0.2f) - m4.x) * inv4.x;
            a4.y = __expf(lrelu(av.y + ad4.y, 0.2f) - m4.y) * inv4.y;
            a4.z = __expf(lrelu(av.z + ad4.z, 0.2f) - m4.z) * inv4.z;
            a4.w = __expf(lrelu(av.w + ad4.w, 0.2f) - m4.w) * inv4.w;
            s_src[w][lane] = src;
            *(float4*)&s_alpha[w][lane * 4] = a4;
        }
        __syncwarp();
        int lim = min(32, cntE - p0);
        int j = 0;
        for (; j + 2 <= lim; j += 2) {
            int   t0 = s_src[w][j],         t1 = s_src[w][j + 1];
            float a0 = s_alpha[w][j * 4 + h], a1 = s_alpha[w][(j + 1) * 4 + h];
            float4 v0 = *(const float4*)&d_h[t0 * 128 + lane * 4];
            float4 v1 = *(const float4*)&d_h[t1 * 128 + lane * 4];
            acc.x += v0.x * a0 + v1.x * a1;
            acc.y += v0.y * a0 + v1.y * a1;
            acc.z += v0.z * a0 + v1.z * a1;
            acc.w += v0.w * a0 + v1.w * a1;
        }
        if (j < lim) {
            int   t0 = s_src[w][j];
            float a0 = s_alpha[w][j * 4 + h];
            float4 v0 = *(const float4*)&d_h[t0 * 128 + lane * 4];
            acc.x += v0.x * a0; acc.y += v0.y * a0;
            acc.z += v0.z * a0; acc.w += v0.w * a0;
        }
        __syncwarp();
    }
    float4 bb = *(const float4*)&bg[lane * 4];
    float4 o;
    o.x = lrelu(acc.x + bb.x, 0.01f);
    o.y = lrelu(acc.y + bb.y, 0.01f);
    o.z = lrelu(acc.z + bb.z, 0.01f);
    o.w = lrelu(acc.w + bb.w, 0.01f);
    *(float4*)&d_gat[d * 128 + lane * 4] = o;
}

// ---------------- GEMM1: h1 = d_gat @ W2 (128 -> 64) ---------------------------
__global__ void k_gemm1(const float* __restrict__ W2) {
    __shared__ float Ws[64 * 132];                 // [o][k] padded
    for (int i = threadIdx.x; i < 128 * 64; i += 256) {
        int k = i >> 6, o = i & 63;
        Ws[o * 132 + k] = W2[i];
    }
    __syncthreads();
    int o = threadIdx.x & 63, nl = threadIdx.x >> 6;
    for (int n0 = blockIdx.x * 4; n0 < NN; n0 += gridDim.x * 4) {
        int node = n0 + nl;
        if (node < NN) {
            const float4* g4 = (const float4*)&d_gat[node * 128];
            float acc = 0.f;
            #pragma unroll
            for (int kk = 0; kk < 32; kk++) {
                float4 g = g4[kk];
                float4 ww = *(const float4*)&Ws[o * 132 + kk * 4];
                acc += g.x * ww.x + g.y * ww.y + g.z * ww.z + g.w * ww.w;
            }
            d_h1[node * 64 + o] = acc;
        }
    }
}

// ---------------- GCN1 gather (warp per node) ----------------------------------
__global__ void k_gcn1(const float* __restrict__ b2) {
    __shared__ int   s_src[8][32];
    __shared__ float s_dv [8][32];
    int gw = (blockIdx.x * 256 + threadIdx.x) >> 5;
    if (gw >= NN) return;
    int lane = threadIdx.x & 31;
    int w = (threadIdx.x >> 5) & 7;
    int d = gw;
    float did = d_dinv[d];

    float2 hv = *(const float2*)&d_h1[d * 64 + lane * 2];
    float2 acc; acc.x = hv.x * did; acc.y = hv.y * did;

    int start = d_off[d];
    int cntE  = d_degi[d];
    for (int p0 = 0; p0 < cntE; p0 += 32) {
        if (p0 + lane < cntE) {
            int src = d_csr[start + p0 + lane];
            s_src[w][lane] = src;
            s_dv [w][lane] = d_dinv[src];
        }
        __syncwarp();
        int lim = min(32, cntE - p0);
        int j = 0;
        for (; j + 4 <= lim; j += 4) {
            int   t0 = s_src[w][j],   t1 = s_src[w][j+1], t2 = s_src[w][j+2], t3 = s_src[w][j+3];
            float u0 = s_dv [w][j],   u1 = s_dv [w][j+1], u2 = s_dv [w][j+2], u3 = s_dv [w][j+3];
            float2 v0 = *(const float2*)&d_h1[t0 * 64 + lane * 2];
            float2 v1 = *(const float2*)&d_h1[t1 * 64 + lane * 2];
            float2 v2 = *(const float2*)&d_h1[t2 * 64 + lane * 2];
            float2 v3 = *(const float2*)&d_h1[t3 * 64 + lane * 2];
            acc.x += v0.x * u0 + v1.x * u1 + v2.x * u2 + v3.x * u3;
            acc.y += v0.y * u0 + v1.y * u1 + v2.y * u2 + v3.y * u3;
        }
        for (; j < lim; j++) {
            int   t0 = s_src[w][j];
            float u0 = s_dv [w][j];
            float2 v0 = *(const float2*)&d_h1[t0 * 64 + lane * 2];
            acc.x += v0.x * u0; acc.y += v0.y * u0;
        }
        __syncwarp();
    }
    float2 o;
    o.x = lrelu(acc.x * did + b2[lane * 2 + 0], 0.01f);
    o.y = lrelu(acc.y * did + b2[lane * 2 + 1], 0.01f);
    *(float2*)&d_o2[d * 64 + lane * 2] = o;
}

// ---------------- GEMM2: h2 = d_o2 @ W3 (64 -> 128) ----------------------------
__global__ void k_gemm2(const float* __restrict__ W3) {
    __shared__ float Ws[128 * 68];                 // [o][k] padded
    for (int i = threadIdx.x; i < 64 * 128; i += 256) {
        int k = i >> 7, o = i & 127;
        Ws[o * 68 + k] = W3[i];
    }
    __syncthreads();
    int o = threadIdx.x & 127, nl = threadIdx.x >> 7;
    for (int n0 = blockIdx.x * 2; n0 < NN; n0 += gridDim.x * 2) {
        int node = n0 + nl;
        if (node < NN) {
            const float4* g4 = (const float4*)&d_o2[node * 64];
            float acc = 0.f;
            #pragma unroll
            for (int kk = 0; kk < 16; kk++) {
                float4 g = g4[kk];
                float4 ww = *(const float4*)&Ws[o * 68 + kk * 4];
                acc += g.x * ww.x + g.y * ww.y + g.z * ww.z + g.w * ww.w;
            }
            d_h2[node * 128 + o] = acc;
        }
    }
}

// ---------------- GCN2 gather + fused pool (warp per node) ---------------------
__global__ void k_gcn2pool(const float* __restrict__ b3, const int* __restrict__ batch) {
    __shared__ int   s_src[8][32];
    __shared__ float s_dv [8][32];
    int gw = (blockIdx.x * 256 + threadIdx.x) >> 5;
    if (gw >= NN) return;
    int lane = threadIdx.x & 31;
    int w = (threadIdx.x >> 5) & 7;
    int d = gw;
    float did = d_dinv[d];

    float4 hv = *(const float4*)&d_h2[d * 128 + lane * 4];
    float4 acc;
    acc.x = hv.x * did; acc.y = hv.y * did; acc.z = hv.z * did; acc.w = hv.w * did;

    int start = d_off[d];
    int cntE  = d_degi[d];
    for (int p0 = 0; p0 < cntE; p0 += 32) {
        if (p0 + lane < cntE) {
            int src = d_csr[start + p0 + lane];
            s_src[w][lane] = src;
            s_dv [w][lane] = d_dinv[src];
        }
        __syncwarp();
        int lim = min(32, cntE - p0);
        int j = 0;
        for (; j + 4 <= lim; j += 4) {
            int   t0 = s_src[w][j],   t1 = s_src[w][j+1], t2 = s_src[w][j+2], t3 = s_src[w][j+3];
            float u0 = s_dv [w][j],   u1 = s_dv [w][j+1], u2 = s_dv [w][j+2], u3 = s_dv [w][j+3];
            float4 v0 = *(const float4*)&d_h2[t0 * 128 + lane * 4];
            float4 v1 = *(const float4*)&d_h2[t1 * 128 + lane * 4];
            float4 v2 = *(const float4*)&d_h2[t2 * 128 + lane * 4];
            float4 v3 = *(const float4*)&d_h2[t3 * 128 + lane * 4];
            acc.x += v0.x * u0 + v1.x * u1 + v2.x * u2 + v3.x * u3;
            acc.y += v0.y * u0 + v1.y * u1 + v2.y * u2 + v3.y * u3;
            acc.z += v0.z * u0 + v1.z * u1 + v2.z * u2 + v3.z * u3;
            acc.w += v0.w * u0 + v1.w * u1 + v2.w * u2 + v3.w * u3;
        }
        for (; j < lim; j++) {
            int   t0 = s_src[w][j];
            float u0 = s_dv [w][j];
            float4 v0 = *(const float4*)&d_h2[t0 * 128 + lane * 4];
            acc.x += v0.x * u0; acc.y += v0.y * u0;
            acc.z += v0.z * u0; acc.w += v0.w * u0;
        }
        __syncwarp();
    }
    float4 bb = *(const float4*)&b3[lane * 4];
    float ox = lrelu(acc.x * did + bb.x, 0.01f);
    float oy = lrelu(acc.y * did + bb.y, 0.01f);
    float oz = lrelu(acc.z * did + bb.z, 0.01f);
    float ow = lrelu(acc.w * did + bb.w, 0.01f);
    int b = batch[d];
    redAdd4(&d_pool[b * 128 + lane * 4], ox, oy, oz, ow);
}

// ---------------- sequence branch ----------------------------------------------
__global__ void k_seq1(const float* __restrict__ seq, const float* __restrict__ w,
                       const float* __restrict__ bias,
                       const float* __restrict__ g, const float* __restrict__ be,
                       const float* __restrict__ m, const float* __restrict__ v) {
    int idx = blockIdx.x * 256 + threadIdx.x;       // BB*64*18
    int b = idx / 1152, r = idx % 1152, co = r / 18, t = r % 18;
    float acc = bias[co];
    #pragma unroll 5
    for (int ci = 0; ci < 30; ci++) {
        const float* sp = &seq[b * 600 + ci * 20 + t];
        const float* wp = &w[(co * 30 + ci) * 3];
        acc += sp[0] * wp[0] + sp[1] * wp[1] + sp[2] * wp[2];
    }
    acc = (acc - m[co]) * rsqrtf(v[co] + 1e-5f) * g[co] + be[co];
    d_s1[idx] = lrelu(acc, 0.01f);
}

__global__ void k_seq2(const float* __restrict__ w, const float* __restrict__ bias,
                       const float* __restrict__ g, const float* __restrict__ be,
                       const float* __restrict__ m, const float* __restrict__ v) {
    int idx = blockIdx.x * 256 + threadIdx.x;       // BB*64*16
    int b = idx >> 10, r = idx & 1023, co = r >> 4, t = r & 15;
    float acc = bias[co];
    #pragma unroll 8
    for (int ci = 0; ci < 64; ci++) {
        const float* sp = &d_s1[b * 1152 + ci * 18 + t];
        const float* wp = &w[(co * 64 + ci) * 3];
        acc += sp[0] * wp[0] + sp[1] * wp[1] + sp[2] * wp[2];
    }
    acc = (acc - m[co]) * rsqrtf(v[co] + 1e-5f) * g[co] + be[co];
    d_s2[idx] = lrelu(acc, 0.01f);
}

__global__ void k_fc1(const float* __restrict__ W, const float* __restrict__ bias) {
    int tid = threadIdx.x;                          // grid 64 x 256
    int o = tid & 63, q = tid >> 6;
    int b0 = blockIdx.x * 16 + q * 4;
    float a0 = bias[o], a1 = a0, a2 = a0, a3 = a0;
    #pragma unroll 4
    for (int k = 0; k < 1024; k++) {
        float ww = W[k * 64 + o];
        a0 += d_s2[(b0 + 0) * 1024 + k] * ww;
        a1 += d_s2[(b0 + 1) * 1024 + k] * ww;
        a2 += d_s2[(b0 + 2) * 1024 + k] * ww;
        a3 += d_s2[(b0 + 3) * 1024 + k] * ww;
    }
    d_fc[(b0 + 0) * 64 + o] = a0;
    d_fc[(b0 + 1) * 64 + o] = a1;
    d_fc[(b0 + 2) * 64 + o] = a2;
    d_fc[(b0 + 3) * 64 + o] = a3;
}

// ---------------- fusion + classifier head -------------------------------------
__global__ void k_head(const float* __restrict__ fusW, const float* __restrict__ fusb,
                       const float* __restrict__ c1W, const float* __restrict__ c1b,
                       const float* __restrict__ c3W, const float* __restrict__ c3b,
                       float* __restrict__ out) {
    __shared__ float comb[192], t1[128], t2[64];
    int b = blockIdx.x, tid = threadIdx.x;          // 128 threads
    if (tid < 128) comb[tid] = d_pool[b * 128 + tid] / fmaxf(d_cnt[b], 1.0f);
    if (tid < 64)  comb[128 + tid] = d_fc[b * 64 + tid];
    __syncthreads();
    float acc = fusb[tid];
    #pragma unroll 8
    for (int k = 0; k < 192; k++) acc += comb[k] * fusW[k * 128 + tid];
    t1[tid] = lrelu(acc, 0.01f);
    __syncthreads();
    if (tid < 64) {
        float a = c1b[tid];
        #pragma unroll 8
        for (int k = 0; k < 128; k++) a += t1[k] * c1W[k * 64 + tid];
        t2[tid] = lrelu(a, 0.01f);
    }
    __syncthreads();
    if (tid == 0) {
        float a = c3b[0];
        #pragma unroll 8
        for (int k = 0; k < 64; k++) a += t2[k] * c3W[k];
        out[b] = a;
    }
}

// ---------------- launch --------------------------------------------------------
extern "C" void kernel_launch(void* const* d_in, const int* in_sizes, int n_in,
                              void* d_out, int out_size) {
    const float* x     = (const float*)d_in[0];
    const int*   ei    = (const int*)  d_in[1];
    const int*   batch = (const int*)  d_in[2];
    const float* seq   = (const float*)d_in[3];
    const float* Wg    = (const float*)d_in[4];
    const float* atts  = (const float*)d_in[5];
    const float* attd  = (const float*)d_in[6];
    const float* bg    = (const float*)d_in[7];
    const float* W2    = (const float*)d_in[8];
    const float* b2    = (const float*)d_in[9];
    const float* W3    = (const float*)d_in[10];
    const float* b3    = (const float*)d_in[11];
    const float* c1w   = (const float*)d_in[12];
    const float* c1bv  = (const float*)d_in[13];
    const float* c2w   = (const float*)d_in[14];
    const float* c2bv  = (const float*)d_in[15];
    const float* bn1g  = (const float*)d_in[16];
    const float* bn1b  = (const float*)d_in[17];
    const float* bn1m  = (const float*)d_in[18];
    const float* bn1v  = (const float*)d_in[19];
    const float* bn2g  = (const float*)d_in[20];
    const float* bn2b  = (const float*)d_in[21];
    const float* bn2m  = (const float*)d_in[22];
    const float* bn2v  = (const float*)d_in[23];
    const float* fcW   = (const float*)d_in[24];
    const float* fcb   = (const float*)d_in[25];
    const float* fusW  = (const float*)d_in[26];
    const float* fusb  = (const float*)d_in[27];
    const float* cls1W = (const float*)d_in[28];
    const float* cls1b = (const float*)d_in[29];
    const float* cls3W = (const float*)d_in[30];
    const float* cls3b = (const float*)d_in[31];
    float* out = (float*)d_out;

    k_init  <<<512, 256>>>();
    k_node  <<<50000, 256>>>(x, Wg, atts, attd);
    k_hist  <<<(EE + 255) / 256, 256>>>(ei, batch);
    k_scanA <<<SCAN_B, 1024>>>();
    k_scanB <<<1, 128>>>();
    k_scanC <<<SCAN_B, 1024>>>();
    k_fill  <<<(EE + 255) / 256, 256>>>(ei);
    k_gat   <<<12500, 256>>>(bg);
    k_gemm1 <<<1184, 256>>>(W2);
    k_gcn1  <<<12500, 256>>>(b2);
    k_gemm2 <<<1184, 256>>>(W3);
    k_gcn2pool<<<12500, 256>>>(b3, batch);
    k_seq1  <<<BB * 1152 / 256, 256>>>(seq, c1w, c1bv, bn1g, bn1b, bn1m, bn1v);
    k_seq2  <<<BB * 1024 / 256, 256>>>(c2w, c2bv, bn2g, bn2b, bn2m, bn2v);
    k_fc1   <<<64, 256>>>(fcW, fcb);
    k_head  <<<BB, 128>>>(fusW, fusb, cls1W, cls1b, cls3W, cls3b, out);
}